// round 10
// baseline (speedup 1.0000x reference)
#include <cuda_runtime.h>
#include <cstdint>

#define MODELS 8
#define BATCH 65536
#define CHOICE 100
#define WARP_CUST 4
#define CPB 32                         // 8 warps * 4 customers
#define THREADS 256
#define NBLK (BATCH / CPB)             // 2048
#define ZSTRIDE ((size_t)BATCH * CHOICE)

__device__ float g_partials[NBLK];
__device__ unsigned int g_count;       // zero-init; finisher resets

// sum of exps of one row-tile share (3 f4 + masked 4th), then octet reduce
__device__ __forceinline__ float expsum_octet(float4 c0, float4 c1, float4 c2,
                                              float4 c3, float mo) {
    float a0 = 0.f, a1 = 0.f;
    a0 += __expf(c0.x) + __expf(c0.z);  a1 += __expf(c0.y) + __expf(c0.w);
    a0 += __expf(c1.x) + __expf(c1.z);  a1 += __expf(c1.y) + __expf(c1.w);
    a0 += __expf(c2.x) + __expf(c2.z);  a1 += __expf(c2.y) + __expf(c2.w);
    float e4 = (__expf(c3.x) + __expf(c3.z)) + (__expf(c3.y) + __expf(c3.w));
    float acc = a0 + a1 + mo * e4;
    acc += __shfl_xor_sync(0xffffffffu, acc, 1);
    acc += __shfl_xor_sync(0xffffffffu, acc, 2);
    acc += __shfl_xor_sync(0xffffffffu, acc, 4);
    return acc;
}

extern "C" __global__ void __launch_bounds__(THREADS, 5)
mmnl_main(const float* __restrict__ x, const float* __restrict__ y,
          const float* __restrict__ z, const float* __restrict__ alpha,
          const float* __restrict__ u_prev, const float* __restrict__ u,
          float* __restrict__ out)
{
    const int tid  = threadIdx.x;
    const int bid  = blockIdx.x;
    const int w    = tid >> 5;
    const int lane = tid & 31;
    const int c    = lane >> 3;        // customer within warp (0..3)
    const int o    = lane & 7;         // octant of the row
    const float mo = (o == 0) ? 1.f : 0.f;

    __shared__ float s_alpha[MODELS], s_eup[MODELS], s_wsum[8];
    __shared__ float s_eu;
    __shared__ bool  s_last;
    if (tid < MODELS) { s_alpha[tid] = alpha[tid]; s_eup[tid] = __expf(u_prev[tid]); }
    if (tid == MODELS) s_eu = __expf(u[0]);
    __syncthreads();

    const size_t rowoff = ((size_t)bid * CPB + (size_t)w * WARP_CUST + c) * CHOICE;
    const float* yrow = y + rowoff;
    const float* xrow = x + rowoff;
    const float* zrow = z + rowoff;

    // ---- tile 0: y — one-hot locate (direct LDG) ----
    bool has; int c_star;
    {
        const float4* y4 = (const float4*)yrow;
        float4 v0 = y4[o], v1 = y4[o + 8], v2 = y4[o + 16];
        float4 v3 = make_float4(0.f, 0.f, 0.f, 0.f);
        if (o == 0) v3 = y4[24];

        float sy = 0.f, sl = 0.f;
        {   // f4 slots s=0,1,2 at cols 4o+32s
            float cb;
            cb = (float)(4 * o);
            sy += (v0.x + v0.y) + (v0.z + v0.w);
            sl = fmaf(v0.x, cb, sl); sl = fmaf(v0.y, cb + 1.f, sl);
            sl = fmaf(v0.z, cb + 2.f, sl); sl = fmaf(v0.w, cb + 3.f, sl);
            cb = (float)(4 * o + 32);
            sy += (v1.x + v1.y) + (v1.z + v1.w);
            sl = fmaf(v1.x, cb, sl); sl = fmaf(v1.y, cb + 1.f, sl);
            sl = fmaf(v1.z, cb + 2.f, sl); sl = fmaf(v1.w, cb + 3.f, sl);
            cb = (float)(4 * o + 64);
            sy += (v2.x + v2.y) + (v2.z + v2.w);
            sl = fmaf(v2.x, cb, sl); sl = fmaf(v2.y, cb + 1.f, sl);
            sl = fmaf(v2.z, cb + 2.f, sl); sl = fmaf(v2.w, cb + 3.f, sl);
        }
        float sy4 = (v3.x + v3.y) + (v3.z + v3.w);
        float sl4 = fmaf(v3.x, 96.f, fmaf(v3.y, 97.f,
                    fmaf(v3.z, 98.f, v3.w * 99.f)));
        sy += mo * sy4;
        sl  = fmaf(mo, sl4, sl);
        float comb = fmaf(sy, 1024.f, sl);
        comb += __shfl_xor_sync(0xffffffffu, comb, 1);
        comb += __shfl_xor_sync(0xffffffffu, comb, 2);
        comb += __shfl_xor_sync(0xffffffffu, comb, 4);
        has    = (comb > 512.f);
        c_star = has ? ((int)rintf(comb) - 1024) : 0;
    }

    // ---- prime prefetch: tile 1 (x) ----
    float4 p0, p1, p2; float pp;
    {
        const float4* x4 = (const float4*)xrow;
        p0 = x4[o]; p1 = x4[o + 8]; p2 = x4[o + 16];
        pp = xrow[c_star];
    }

    float sex, xy, g = 0.f;

    // ---- tile 1: x; prefetch z0 ----
    {
        float4 c0 = p0, c1 = p1, c2 = p2; float cp = pp;
        const float4* n4 = (const float4*)zrow;
        p0 = n4[o]; p1 = n4[o + 8]; p2 = n4[o + 16];
        pp = zrow[c_star];
        float4 c3 = make_float4(0.f, 0.f, 0.f, 0.f);
        if (o == 0) c3 = ((const float4*)xrow)[24];
        float acc = expsum_octet(c0, c1, c2, c3, mo);
        sex = acc; xy = cp;
    }

    // ---- z tiles: compute z_m, prefetch z_{m+1} ----
#pragma unroll
    for (int m = 0; m < MODELS; m++) {
        float4 c0 = p0, c1 = p1, c2 = p2; float cp = pp;
        if (m < MODELS - 1) {
            const float* nr = zrow + (size_t)(m + 1) * ZSTRIDE;
            const float4* n4 = (const float4*)nr;
            p0 = n4[o]; p1 = n4[o + 8]; p2 = n4[o + 16];
            pp = nr[c_star];
        }
        float4 c3 = make_float4(0.f, 0.f, 0.f, 0.f);
        if (o == 0)
            c3 = ((const float4*)(zrow + (size_t)m * ZSTRIDE))[24];
        float acc = expsum_octet(c0, c1, c2, c3, mo);
        float eup = s_eup[m];
        float num = has ? __expf(cp) : eup;
        g = fmaf(s_alpha[m], __fdividef(num, eup + acc), g);
    }

    // ---- per-customer term; all 8 octet lanes hold identical tval ----
    float eu   = s_eu;
    float numx = has ? __expf(xy) : eu;
    float tval = __fdividef(numx, (eu + sex) * g);

    float v = tval;
#pragma unroll
    for (int of = 16; of > 0; of >>= 1)
        v += __shfl_xor_sync(0xffffffffu, v, of);
    if (lane == 0) s_wsum[w] = v * 0.125f;     // octets counted 8x
    __syncthreads();

    if (w == 0) {
        float a = (lane < 8) ? s_wsum[lane] : 0.f;
#pragma unroll
        for (int of = 4; of > 0; of >>= 1)
            a += __shfl_xor_sync(0xffffffffu, a, of);
        if (lane == 0) {
            g_partials[bid] = a;
            __threadfence();
            s_last = (atomicAdd(&g_count, 1u) == (unsigned)(NBLK - 1));
        }
    }
    __syncthreads();

    if (s_last) {
        __threadfence();
        __shared__ float red[THREADS];
        float a = 0.f;
        for (int i = tid; i < NBLK; i += THREADS) a += __ldcg(&g_partials[i]);
        red[tid] = a;
        __syncthreads();
#pragma unroll
        for (int s = THREADS / 2; s > 0; s >>= 1) {
            if (tid < s) red[tid] += red[tid + s];
            __syncthreads();
        }
        if (tid == 0) {
            out[0]  = -red[0] / (float)BATCH;
            g_count = 0;                        // reset for next graph replay
        }
    }
}

extern "C" void kernel_launch(void* const* d_in, const int* in_sizes, int n_in,
                              void* d_out, int out_size)
{
    const float* x      = (const float*)d_in[0];
    const float* y      = (const float*)d_in[1];
    const float* z      = (const float*)d_in[2];
    const float* alpha  = (const float*)d_in[3];
    const float* u_prev = (const float*)d_in[4];
    const float* u      = (const float*)d_in[5];
    float* out = (float*)d_out;

    mmnl_main<<<NBLK, THREADS>>>(x, y, z, alpha, u_prev, u, out);
}

// round 11
// speedup vs baseline: 1.0413x; 1.0413x over previous
#include <cuda_runtime.h>
#include <cstdint>

#define MODELS 8
#define BATCH 65536
#define CHOICE 100
#define WARP_CUST 4
#define CPB 16                          // 4 warps * 4 customers
#define THREADS 128
#define NBLK (BATCH / CPB)              // 4096
#define ZSTRIDE ((size_t)BATCH * CHOICE)

__device__ float g_partials[NBLK];
__device__ unsigned int g_count;        // zero-init; finisher resets

// stage load: lane's 3 f4 slots (o, o+8, o+16) + predicated slot 24 (o==0)
#define LOADS(S0, S1, S2, S3, BASE) do {                 \
    const float4* _p = (const float4*)(BASE);            \
    (S0) = __ldcs(_p + o);                               \
    (S1) = __ldcs(_p + o + 8);                           \
    (S2) = __ldcs(_p + o + 16);                          \
    if (o == 0) (S3) = __ldcs(_p + 24);                  \
} while (0)

__device__ __forceinline__ float expsum_octet(float4 c0, float4 c1, float4 c2,
                                              float4 c3, float mo) {
    float a0 = 0.f, a1 = 0.f;
    a0 += __expf(c0.x) + __expf(c0.z);  a1 += __expf(c0.y) + __expf(c0.w);
    a0 += __expf(c1.x) + __expf(c1.z);  a1 += __expf(c1.y) + __expf(c1.w);
    a0 += __expf(c2.x) + __expf(c2.z);  a1 += __expf(c2.y) + __expf(c2.w);
    float e4 = (__expf(c3.x) + __expf(c3.z)) + (__expf(c3.y) + __expf(c3.w));
    float acc = a0 + a1 + mo * e4;
    acc += __shfl_xor_sync(0xffffffffu, acc, 1);
    acc += __shfl_xor_sync(0xffffffffu, acc, 2);
    acc += __shfl_xor_sync(0xffffffffu, acc, 4);
    return acc;
}

extern "C" __global__ void __launch_bounds__(THREADS, 8)
mmnl_main(const float* __restrict__ x, const float* __restrict__ y,
          const float* __restrict__ z, const float* __restrict__ alpha,
          const float* __restrict__ u_prev, const float* __restrict__ u,
          float* __restrict__ out)
{
    const int tid  = threadIdx.x;
    const int bid  = blockIdx.x;
    const int w    = tid >> 5;          // warp 0..3
    const int lane = tid & 31;
    const int c    = lane >> 3;         // customer within warp (0..3)
    const int o    = lane & 7;          // octant of the row
    const float mo = (o == 0) ? 1.f : 0.f;

    __shared__ float s_alpha[MODELS], s_eup[MODELS], s_wsum[4];
    __shared__ float s_eu;
    __shared__ bool  s_last;
    if (tid < MODELS) { s_alpha[tid] = alpha[tid]; s_eup[tid] = __expf(u_prev[tid]); }
    if (tid == MODELS) s_eu = __expf(u[0]);
    __syncthreads();

    const size_t rowoff = ((size_t)bid * CPB + (size_t)w * WARP_CUST + c) * CHOICE;
    const float* yrow = y + rowoff;
    const float* xrow = x + rowoff;
    const float* zrow = z + rowoff;

    // two prefetch stages; slot-3 regs stay 0 for lanes o!=0 (never written)
    float4 A0, A1, A2, A3, B0, B1, B2, B3;
    A3 = make_float4(0.f, 0.f, 0.f, 0.f);
    B3 = A3;

    LOADS(A0, A1, A2, A3, yrow);        // tile 0 (y) -> A
    LOADS(B0, B1, B2, B3, xrow);        // tile 1 (x) -> B

    // ---- tile 0: y — one-hot locate from stage A ----
    bool has; int c_star;
    {
        float sy = 0.f, sl = 0.f;
        float cb;
        cb = (float)(4 * o);
        sy += (A0.x + A0.y) + (A0.z + A0.w);
        sl = fmaf(A0.x, cb, sl); sl = fmaf(A0.y, cb + 1.f, sl);
        sl = fmaf(A0.z, cb + 2.f, sl); sl = fmaf(A0.w, cb + 3.f, sl);
        cb = (float)(4 * o + 32);
        sy += (A1.x + A1.y) + (A1.z + A1.w);
        sl = fmaf(A1.x, cb, sl); sl = fmaf(A1.y, cb + 1.f, sl);
        sl = fmaf(A1.z, cb + 2.f, sl); sl = fmaf(A1.w, cb + 3.f, sl);
        cb = (float)(4 * o + 64);
        sy += (A2.x + A2.y) + (A2.z + A2.w);
        sl = fmaf(A2.x, cb, sl); sl = fmaf(A2.y, cb + 1.f, sl);
        sl = fmaf(A2.z, cb + 2.f, sl); sl = fmaf(A2.w, cb + 3.f, sl);
        float sy4 = (A3.x + A3.y) + (A3.z + A3.w);
        float sl4 = fmaf(A3.x, 96.f, fmaf(A3.y, 97.f,
                    fmaf(A3.z, 98.f, A3.w * 99.f)));
        sy += mo * sy4;
        sl  = fmaf(mo, sl4, sl);
        float comb = fmaf(sy, 1024.f, sl);
        comb += __shfl_xor_sync(0xffffffffu, comb, 1);
        comb += __shfl_xor_sync(0xffffffffu, comb, 2);
        comb += __shfl_xor_sync(0xffffffffu, comb, 4);
        has    = (comb > 512.f);
        c_star = has ? ((int)rintf(comb) - 1024) : 0;
    }

    // refill A with z0 (+ pick); A3 for o!=0 remains 0
    float ppA, ppB;
    LOADS(A0, A1, A2, A3, zrow);
    ppA = zrow[c_star];

    // ---- tile 1: x from stage B ----
    float sex, xy, g = 0.f;
    {
        sex = expsum_octet(B0, B1, B2, B3, mo);
        xy  = xrow[c_star];             // L1/L2 hit: line already streamed
    }
    LOADS(B0, B1, B2, B3, zrow + ZSTRIDE);
    ppB = (zrow + ZSTRIDE)[c_star];

    // ---- z tiles: compute z_m (A), z_{m+1} (B); refill 2 ahead ----
#pragma unroll
    for (int m = 0; m < MODELS; m += 2) {
        {
            float acc = expsum_octet(A0, A1, A2, A3, mo);
            float eup = s_eup[m];
            float num = has ? __expf(ppA) : eup;
            g = fmaf(s_alpha[m], __fdividef(num, eup + acc), g);
            if (m + 2 < MODELS) {
                const float* nr = zrow + (size_t)(m + 2) * ZSTRIDE;
                LOADS(A0, A1, A2, A3, nr);
                ppA = nr[c_star];
            }
        }
        {
            float acc = expsum_octet(B0, B1, B2, B3, mo);
            float eup = s_eup[m + 1];
            float num = has ? __expf(ppB) : eup;
            g = fmaf(s_alpha[m + 1], __fdividef(num, eup + acc), g);
            if (m + 3 < MODELS) {
                const float* nr = zrow + (size_t)(m + 3) * ZSTRIDE;
                LOADS(B0, B1, B2, B3, nr);
                ppB = nr[c_star];
            }
        }
    }

    // ---- per-customer term; all 8 octet lanes hold identical tval ----
    float eu   = s_eu;
    float numx = has ? __expf(xy) : eu;
    float tval = __fdividef(numx, (eu + sex) * g);

    float v = tval;
#pragma unroll
    for (int of = 16; of > 0; of >>= 1)
        v += __shfl_xor_sync(0xffffffffu, v, of);
    if (lane == 0) s_wsum[w] = v * 0.125f;  // octets counted 8x
    __syncthreads();

    if (w == 0) {
        float a = (lane < 4) ? s_wsum[lane] : 0.f;
        a += __shfl_xor_sync(0xffffffffu, a, 1);
        a += __shfl_xor_sync(0xffffffffu, a, 2);
        if (lane == 0) {
            g_partials[bid] = a;
            __threadfence();
            s_last = (atomicAdd(&g_count, 1u) == (unsigned)(NBLK - 1));
        }
    }
    __syncthreads();

    if (s_last) {
        __threadfence();
        __shared__ float red[THREADS];
        float a = 0.f;
        for (int i = tid; i < NBLK; i += THREADS) a += __ldcg(&g_partials[i]);
        red[tid] = a;
        __syncthreads();
#pragma unroll
        for (int s = THREADS / 2; s > 0; s >>= 1) {
            if (tid < s) red[tid] += red[tid + s];
            __syncthreads();
        }
        if (tid == 0) {
            out[0]  = -red[0] / (float)BATCH;
            g_count = 0;                // reset for next graph replay
        }
    }
}

extern "C" void kernel_launch(void* const* d_in, const int* in_sizes, int n_in,
                              void* d_out, int out_size)
{
    const float* x      = (const float*)d_in[0];
    const float* y      = (const float*)d_in[1];
    const float* z      = (const float*)d_in[2];
    const float* alpha  = (const float*)d_in[3];
    const float* u_prev = (const float*)d_in[4];
    const float* u      = (const float*)d_in[5];
    float* out = (float*)d_out;

    mmnl_main<<<NBLK, THREADS>>>(x, y, z, alpha, u_prev, u, out);
}

// round 12
// speedup vs baseline: 1.1341x; 1.0892x over previous
#include <cuda_runtime.h>
#include <cstdint>

#define MODELS 8
#define BATCH 65536
#define CHOICE 100
#define WARP_CUST 4
#define CPB 16                          // 4 warps * 4 customers
#define THREADS 128
#define NG 4                            // groups per block
#define NBLK (BATCH / (CPB * NG))       // 1024 -> single wave @8/SM
#define GSTEP (CPB * CHOICE)            // 1600 floats per group
#define ZSTRIDE ((size_t)BATCH * CHOICE)

__device__ float g_partials[NBLK];
__device__ unsigned int g_count;        // zero-init; finisher resets

// stage load: lane's 3 f4 slots (o, o+8, o+16) + predicated slot 24 (o==0)
#define LOADS(S0, S1, S2, S3, BASE) do {                 \
    const float4* _p = (const float4*)(BASE);            \
    (S0) = __ldcs(_p + o);                               \
    (S1) = __ldcs(_p + o + 8);                           \
    (S2) = __ldcs(_p + o + 16);                          \
    if (o == 0) (S3) = __ldcs(_p + 24);                  \
} while (0)

__device__ __forceinline__ float expsum_octet(float4 c0, float4 c1, float4 c2,
                                              float4 c3, float mo) {
    float a0 = 0.f, a1 = 0.f;
    a0 += __expf(c0.x) + __expf(c0.z);  a1 += __expf(c0.y) + __expf(c0.w);
    a0 += __expf(c1.x) + __expf(c1.z);  a1 += __expf(c1.y) + __expf(c1.w);
    a0 += __expf(c2.x) + __expf(c2.z);  a1 += __expf(c2.y) + __expf(c2.w);
    float e4 = (__expf(c3.x) + __expf(c3.z)) + (__expf(c3.y) + __expf(c3.w));
    float acc = a0 + a1 + mo * e4;
    acc += __shfl_xor_sync(0xffffffffu, acc, 1);
    acc += __shfl_xor_sync(0xffffffffu, acc, 2);
    acc += __shfl_xor_sync(0xffffffffu, acc, 4);
    return acc;
}

extern "C" __global__ void __launch_bounds__(THREADS, 8)
mmnl_main(const float* __restrict__ x, const float* __restrict__ y,
          const float* __restrict__ z, const float* __restrict__ alpha,
          const float* __restrict__ u_prev, const float* __restrict__ u,
          float* __restrict__ out)
{
    const int tid  = threadIdx.x;
    const int bid  = blockIdx.x;
    const int w    = tid >> 5;          // warp 0..3
    const int lane = tid & 31;
    const int c    = lane >> 3;         // customer within warp (0..3)
    const int o    = lane & 7;          // octant of the row
    const float mo = (o == 0) ? 1.f : 0.f;

    __shared__ float s_alpha[MODELS], s_eup[MODELS], s_wsum[4];
    __shared__ float s_eu;
    __shared__ bool  s_last;
    if (tid < MODELS) { s_alpha[tid] = alpha[tid]; s_eup[tid] = __expf(u_prev[tid]); }
    if (tid == MODELS) s_eu = __expf(u[0]);
    __syncthreads();

    size_t rowoff =
        ((size_t)bid * (CPB * NG) + (size_t)w * WARP_CUST + c) * CHOICE;
    const float* yrow = y + rowoff;
    const float* xrow = x + rowoff;
    const float* zrow = z + rowoff;

    // two prefetch stages; slot-3 regs stay 0 for lanes o!=0 (never written)
    float4 A0, A1, A2, A3, B0, B1, B2, B3;
    A3 = make_float4(0.f, 0.f, 0.f, 0.f);
    B3 = A3;

    LOADS(A0, A1, A2, A3, yrow);        // group 0: y -> A
    LOADS(B0, B1, B2, B3, xrow);        // group 0: x -> B

    float tsum = 0.f;

    for (int it = 0; it < NG; ++it) {
        const bool lastg = (it == NG - 1);

        // ---- y locate from stage A ----
        bool has; int c_star;
        {
            float sy = 0.f, sl = 0.f;
            float cb;
            cb = (float)(4 * o);
            sy += (A0.x + A0.y) + (A0.z + A0.w);
            sl = fmaf(A0.x, cb, sl); sl = fmaf(A0.y, cb + 1.f, sl);
            sl = fmaf(A0.z, cb + 2.f, sl); sl = fmaf(A0.w, cb + 3.f, sl);
            cb = (float)(4 * o + 32);
            sy += (A1.x + A1.y) + (A1.z + A1.w);
            sl = fmaf(A1.x, cb, sl); sl = fmaf(A1.y, cb + 1.f, sl);
            sl = fmaf(A1.z, cb + 2.f, sl); sl = fmaf(A1.w, cb + 3.f, sl);
            cb = (float)(4 * o + 64);
            sy += (A2.x + A2.y) + (A2.z + A2.w);
            sl = fmaf(A2.x, cb, sl); sl = fmaf(A2.y, cb + 1.f, sl);
            sl = fmaf(A2.z, cb + 2.f, sl); sl = fmaf(A2.w, cb + 3.f, sl);
            float sy4 = (A3.x + A3.y) + (A3.z + A3.w);
            float sl4 = fmaf(A3.x, 96.f, fmaf(A3.y, 97.f,
                        fmaf(A3.z, 98.f, A3.w * 99.f)));
            sy += mo * sy4;
            sl  = fmaf(mo, sl4, sl);
            float comb = fmaf(sy, 1024.f, sl);
            comb += __shfl_xor_sync(0xffffffffu, comb, 1);
            comb += __shfl_xor_sync(0xffffffffu, comb, 2);
            comb += __shfl_xor_sync(0xffffffffu, comb, 4);
            has    = (comb > 512.f);
            c_star = has ? ((int)rintf(comb) - 1024) : 0;
        }

        // refill A <- z0 (+ pick)
        float ppA, ppB;
        LOADS(A0, A1, A2, A3, zrow);
        ppA = zrow[c_star];

        // ---- x from stage B ----
        float sex, xy, g = 0.f;
        sex = expsum_octet(B0, B1, B2, B3, mo);
        xy  = xrow[c_star];
        LOADS(B0, B1, B2, B3, zrow + ZSTRIDE);
        ppB = (zrow + ZSTRIDE)[c_star];

        // ---- z tiles; refills run 2 ahead, cross into next group ----
#pragma unroll
        for (int m = 0; m < MODELS; m += 2) {
            {
                float acc = expsum_octet(A0, A1, A2, A3, mo);
                float eup = s_eup[m];
                float num = has ? __expf(ppA) : eup;
                g = fmaf(s_alpha[m], __fdividef(num, eup + acc), g);
                if (m + 2 < MODELS) {
                    const float* nr = zrow + (size_t)(m + 2) * ZSTRIDE;
                    LOADS(A0, A1, A2, A3, nr);
                    ppA = nr[c_star];
                } else if (!lastg) {
                    LOADS(A0, A1, A2, A3, yrow + GSTEP);   // next group's y
                }
            }
            {
                float acc = expsum_octet(B0, B1, B2, B3, mo);
                float eup = s_eup[m + 1];
                float num = has ? __expf(ppB) : eup;
                g = fmaf(s_alpha[m + 1], __fdividef(num, eup + acc), g);
                if (m + 3 < MODELS) {
                    const float* nr = zrow + (size_t)(m + 3) * ZSTRIDE;
                    LOADS(B0, B1, B2, B3, nr);
                    ppB = nr[c_star];
                } else if (!lastg) {
                    LOADS(B0, B1, B2, B3, xrow + GSTEP);   // next group's x
                }
            }
        }

        // ---- per-customer term (identical across the 8 octet lanes) ----
        float eu   = s_eu;
        float numx = has ? __expf(xy) : eu;
        tsum += __fdividef(numx, (eu + sex) * g);

        yrow += GSTEP; xrow += GSTEP; zrow += GSTEP;
    }

    // ---- one reduction for all NG groups ----
    float v = tsum;
#pragma unroll
    for (int of = 16; of > 0; of >>= 1)
        v += __shfl_xor_sync(0xffffffffu, v, of);
    if (lane == 0) s_wsum[w] = v * 0.125f;  // octets counted 8x
    __syncthreads();

    if (w == 0) {
        float a = (lane < 4) ? s_wsum[lane] : 0.f;
        a += __shfl_xor_sync(0xffffffffu, a, 1);
        a += __shfl_xor_sync(0xffffffffu, a, 2);
        if (lane == 0) {
            g_partials[bid] = a;
            __threadfence();
            s_last = (atomicAdd(&g_count, 1u) == (unsigned)(NBLK - 1));
        }
    }
    __syncthreads();

    if (s_last) {
        __threadfence();
        __shared__ float red[THREADS];
        float a = 0.f;
        for (int i = tid; i < NBLK; i += THREADS) a += __ldcg(&g_partials[i]);
        red[tid] = a;
        __syncthreads();
#pragma unroll
        for (int s = THREADS / 2; s > 0; s >>= 1) {
            if (tid < s) red[tid] += red[tid + s];
            __syncthreads();
        }
        if (tid == 0) {
            out[0]  = -red[0] / (float)BATCH;
            g_count = 0;                // reset for next graph replay
        }
    }
}

extern "C" void kernel_launch(void* const* d_in, const int* in_sizes, int n_in,
                              void* d_out, int out_size)
{
    const float* x      = (const float*)d_in[0];
    const float* y      = (const float*)d_in[1];
    const float* z      = (const float*)d_in[2];
    const float* alpha  = (const float*)d_in[3];
    const float* u_prev = (const float*)d_in[4];
    const float* u      = (const float*)d_in[5];
    float* out = (float*)d_out;

    mmnl_main<<<NBLK, THREADS>>>(x, y, z, alpha, u_prev, u, out);
}